// round 2
// baseline (speedup 1.0000x reference)
#include <cuda_runtime.h>
#include <math.h>

#define BATCH 16
#define CH    64
#define HH    256
#define WW    256
#define NPIX  (BATCH*HH*WW)   /* 1048576 */
#define ROWS  (BATCH*HH)      /* 4096    */

// ---- scratch (device globals: no allocation allowed) ----
__device__ float  g_gbuf[NPIX];     // exp(-sum d^2) image
__device__ float  g_zbuf[NPIX];     // BN1-normalized image
__device__ double g_stats1[2];      // sum, sumsq of g
__device__ float  g_bn1c[2];        // a1, c1 : z = a1*g + c1
__device__ double g_S[9];           // per-tap sums of z (zero-padded shifts)
__device__ double g_P[45];          // upper-tri of 9x9 Gram of neighbor vec
__device__ float  g_w2p[CH*9];      // BN2-folded conv2 weights
__device__ float  g_b2p[CH];        // BN2-folded conv2 bias

// ------------------------------------------------------------------
__global__ void k0_zero() {
    int t = threadIdx.x;
    if (t < 2)  g_stats1[t] = 0.0;
    if (t < 9)  g_S[t]      = 0.0;
    if (t < 45) g_P[t]      = 0.0;
}

// ------------------------------------------------------------------
// K1: conv1 (64ch -> 1ch, 3x3 SAME) + fuzzy + exp  -> g_gbuf, BN1 stats
#define TH1 16
__global__ __launch_bounds__(256)
void k1_conv1(const float* __restrict__ x,  const float* __restrict__ cw1,
              const float* __restrict__ cb1, const float* __restrict__ mu,
              const float* __restrict__ sigma) {
    __shared__ float s[TH1+2][WW];
    __shared__ float sw[CH*9];
    __shared__ float sr1[8], sr2[8];

    int tx = threadIdx.x;
    for (int i = tx; i < CH*9; i += 256) sw[i] = cw1[i];

    int rowstart = blockIdx.x * TH1;      // global row in [0, 4096)
    int b  = rowstart >> 8;
    int y0 = rowstart & 255;
    const float* xb = x + (size_t)b * CH * (HH*WW);

    float acc[TH1];
#pragma unroll
    for (int j = 0; j < TH1; j++) acc[j] = 0.f;

    for (int c = 0; c < CH; c++) {
        const float* xc = xb + (size_t)c * (HH*WW);
        __syncthreads();
#pragma unroll
        for (int r = 0; r < TH1+2; r++) {
            int gy = y0 - 1 + r;
            s[r][tx] = (gy >= 0 && gy < HH) ? xc[gy*WW + tx] : 0.f;
        }
        __syncthreads();
        float w0 = sw[c*9+0], w1 = sw[c*9+1], w2 = sw[c*9+2];
        float w3 = sw[c*9+3], w4 = sw[c*9+4], w5 = sw[c*9+5];
        float w6 = sw[c*9+6], w7 = sw[c*9+7], w8 = sw[c*9+8];
#pragma unroll
        for (int r = 0; r < TH1+2; r++) {
            float C = s[r][tx];
            float L = (tx > 0)     ? s[r][tx-1] : 0.f;
            float R = (tx < WW-1)  ? s[r][tx+1] : 0.f;
            if (r < TH1)            acc[r]   += L*w0 + C*w1 + R*w2;
            if (r >= 1 && r <= TH1) acc[r-1] += L*w3 + C*w4 + R*w5;
            if (r >= 2)             acc[r-2] += L*w6 + C*w7 + R*w8;
        }
    }

    // fuzzy membership + exp
    float bv = cb1[0];
    float m0 = mu[0], m1 = mu[1], m2 = mu[2], m3 = mu[3];
    float i0 = 1.f/sigma[0], i1 = 1.f/sigma[1], i2 = 1.f/sigma[2], i3 = 1.f/sigma[3];
    float lsum = 0.f, lsq = 0.f;
#pragma unroll
    for (int j = 0; j < TH1; j++) {
        float h  = acc[j] + bv;
        float d0 = (h-m0)*i0, d1 = (h-m1)*i1, d2 = (h-m2)*i2, d3 = (h-m3)*i3;
        float t  = d0*d0 + d1*d1 + d2*d2 + d3*d3;
        float gv = expf(-t);
        g_gbuf[(rowstart+j)*WW + tx] = gv;
        lsum += gv;
        lsq  += gv*gv;
    }

    // block reduce -> double atomics
    int lane = tx & 31, wid = tx >> 5;
#pragma unroll
    for (int o = 16; o; o >>= 1) {
        lsum += __shfl_down_sync(0xffffffffu, lsum, o);
        lsq  += __shfl_down_sync(0xffffffffu, lsq,  o);
    }
    if (lane == 0) { sr1[wid] = lsum; sr2[wid] = lsq; }
    __syncthreads();
    if (tx == 0) {
        double S = 0.0, Q = 0.0;
        for (int w = 0; w < 8; w++) { S += (double)sr1[w]; Q += (double)sr2[w]; }
        atomicAdd(&g_stats1[0], S);
        atomicAdd(&g_stats1[1], Q);
    }
}

// ------------------------------------------------------------------
__global__ void k2_bn1(const float* __restrict__ bn1_g, const float* __restrict__ bn1_b) {
    double N    = (double)NPIX;
    double mean = g_stats1[0] / N;
    double var  = g_stats1[1] / N - mean*mean;
    double a    = (double)bn1_g[0] / sqrt(var + 1e-5);
    g_bn1c[0] = (float)a;
    g_bn1c[1] = (float)((double)bn1_b[0] - mean*a);
}

// ------------------------------------------------------------------
// K3: z = a1*g + c1 (write), accumulate S[9] and Gram P[45] of the
// zero-padded 3x3 neighbor vector (exactly matches conv2 SAME padding).
#define TH3 16
__global__ __launch_bounds__(256)
void k3_stats() {
    __shared__ float s[TH3+2][WW];
    __shared__ float sred[8][54];

    float a1 = g_bn1c[0], c1 = g_bn1c[1];
    int tx = threadIdx.x;
    int rowstart = blockIdx.x * TH3;
    int b  = rowstart >> 8;
    int y0 = rowstart & 255;

#pragma unroll
    for (int r = 0; r < TH3+2; r++) {
        int gy = y0 - 1 + r;
        s[r][tx] = (gy >= 0 && gy < HH)
                   ? fmaf(a1, g_gbuf[(b*HH+gy)*WW + tx], c1) : 0.f;
    }
    __syncthreads();
#pragma unroll
    for (int j = 0; j < TH3; j++)
        g_zbuf[(rowstart+j)*WW + tx] = s[j+1][tx];

    float acc[54];
#pragma unroll
    for (int i = 0; i < 54; i++) acc[i] = 0.f;

#pragma unroll
    for (int j = 0; j < TH3; j++) {
        float n[9];
#pragma unroll
        for (int ky = 0; ky < 3; ky++) {
            int r = j + ky;
            float C = s[r][tx];
            float L = (tx > 0)    ? s[r][tx-1] : 0.f;
            float R = (tx < WW-1) ? s[r][tx+1] : 0.f;
            n[ky*3+0] = L; n[ky*3+1] = C; n[ky*3+2] = R;
        }
#pragma unroll
        for (int a = 0; a < 9; a++) acc[a] += n[a];
        int t = 9;
#pragma unroll
        for (int a = 0; a < 9; a++)
#pragma unroll
            for (int bb = a; bb < 9; bb++) { acc[t] += n[a]*n[bb]; t++; }
    }

    int lane = tx & 31, wid = tx >> 5;
#pragma unroll
    for (int k = 0; k < 54; k++) {
        float v = acc[k];
#pragma unroll
        for (int o = 16; o; o >>= 1) v += __shfl_down_sync(0xffffffffu, v, o);
        if (lane == 0) sred[wid][k] = v;
    }
    __syncthreads();
    if (tx < 54) {
        double v = 0.0;
        for (int w = 0; w < 8; w++) v += (double)sred[w][tx];
        if (tx < 9) atomicAdd(&g_S[tx], v);
        else        atomicAdd(&g_P[tx-9], v);
    }
}

// ------------------------------------------------------------------
// K4: analytic BN2 stats from S, P -> fold into conv2 weights/bias.
__global__ void k4_bn2(const float* __restrict__ w2, const float* __restrict__ b2,
                       const float* __restrict__ g2, const float* __restrict__ be2) {
    int o = threadIdx.x;
    if (o >= CH) return;
    double S[9];
    for (int k = 0; k < 9; k++) S[k] = g_S[k];
    double Pm[9][9];
    int t = 0;
    for (int a = 0; a < 9; a++)
        for (int bb = a; bb < 9; bb++) {
            double v = g_P[t++]; Pm[a][bb] = v; Pm[bb][a] = v;
        }
    double w[9];
    for (int k = 0; k < 9; k++) w[k] = (double)w2[o*9+k];
    double bo = (double)b2[o];
    double ws = 0.0;
    for (int k = 0; k < 9; k++) ws += w[k]*S[k];
    double quad = 0.0;
    for (int a = 0; a < 9; a++) {
        double r = 0.0;
        for (int bb = 0; bb < 9; bb++) r += Pm[a][bb]*w[bb];
        quad += w[a]*r;
    }
    double N    = (double)NPIX;
    double mean = (ws + N*bo) / N;
    double m2   = (quad + 2.0*bo*ws + N*bo*bo) / N;
    double var  = m2 - mean*mean;
    double sc   = (double)g2[o] / sqrt(var + 1e-5);
    for (int k = 0; k < 9; k++) g_w2p[o*9+k] = (float)(w[k]*sc);
    g_b2p[o] = (float)(((double)bo - mean)*sc + (double)be2[o]);
}

// ------------------------------------------------------------------
// K5: conv2' (1ch -> 64ch, folded BN2) -> out. 16 channels per block.
#define TH5  16
#define OGRP 16
__global__ __launch_bounds__(256)
void k5_conv2(float* __restrict__ out) {
    __shared__ float s[TH5+2][WW];
    __shared__ float swp[CH*9];
    __shared__ float sbp[CH];

    int tx   = threadIdx.x;
    int tile = blockIdx.x >> 2;          // 256 tiles
    int grp  = blockIdx.x & 3;           // 4 channel groups of 16
    int rowstart = tile * TH5;
    int b  = rowstart >> 8;
    int y0 = rowstart & 255;

    for (int i = tx; i < CH*9; i += 256) swp[i] = g_w2p[i];
    if (tx < CH) sbp[tx] = g_b2p[tx];
#pragma unroll
    for (int r = 0; r < TH5+2; r++) {
        int gy = y0 - 1 + r;
        s[r][tx] = (gy >= 0 && gy < HH) ? g_zbuf[(b*HH+gy)*WW + tx] : 0.f;
    }
    __syncthreads();

    size_t obase = (size_t)b * CH * (HH*WW);
    for (int oo = 0; oo < OGRP; oo++) {
        int o = grp*OGRP + oo;
        float w0 = swp[o*9+0], w1 = swp[o*9+1], w2 = swp[o*9+2];
        float w3 = swp[o*9+3], w4 = swp[o*9+4], w5 = swp[o*9+5];
        float w6 = swp[o*9+6], w7 = swp[o*9+7], w8 = swp[o*9+8];
        float bb = sbp[o];
        float oacc[TH5];
#pragma unroll
        for (int j = 0; j < TH5; j++) oacc[j] = bb;
#pragma unroll
        for (int r = 0; r < TH5+2; r++) {
            float C = s[r][tx];
            float L = (tx > 0)    ? s[r][tx-1] : 0.f;
            float R = (tx < WW-1) ? s[r][tx+1] : 0.f;
            if (r < TH5)            oacc[r]   += L*w0 + C*w1 + R*w2;
            if (r >= 1 && r <= TH5) oacc[r-1] += L*w3 + C*w4 + R*w5;
            if (r >= 2)             oacc[r-2] += L*w6 + C*w7 + R*w8;
        }
        float* op = out + obase + (size_t)o*(HH*WW) + (size_t)y0*WW + tx;
#pragma unroll
        for (int j = 0; j < TH5; j++) op[j*WW] = oacc[j];
    }
}

// ------------------------------------------------------------------
extern "C" void kernel_launch(void* const* d_in, const int* in_sizes, int n_in,
                              void* d_out, int out_size) {
    const float* x   = (const float*)d_in[0];
    const float* w1  = (const float*)d_in[1];
    const float* b1  = (const float*)d_in[2];
    const float* w2  = (const float*)d_in[3];
    const float* b2  = (const float*)d_in[4];
    const float* mu  = (const float*)d_in[5];
    const float* sg  = (const float*)d_in[6];
    const float* g1  = (const float*)d_in[7];
    const float* bb1 = (const float*)d_in[8];
    const float* g2  = (const float*)d_in[9];
    const float* bb2 = (const float*)d_in[10];
    float* out = (float*)d_out;

    k0_zero <<<1, 64>>>();
    k1_conv1<<<ROWS/TH1, 256>>>(x, w1, b1, mu, sg);
    k2_bn1  <<<1, 1>>>(g1, bb1);
    k3_stats<<<ROWS/TH3, 256>>>();
    k4_bn2  <<<1, CH>>>(w2, b2, g2, bb2);
    k5_conv2<<<(ROWS/TH5)*4, 256>>>(out);
}

// round 4
// speedup vs baseline: 1.8792x; 1.8792x over previous
#include <cuda_runtime.h>
#include <math.h>

#define BATCH 16
#define CH    64
#define HH    256
#define WW    256
#define NPIX  (BATCH*HH*WW)   /* 1048576 */
#define ROWS  (BATCH*HH)      /* 4096    */

// ---- scratch (device globals: no allocation allowed) ----
__device__ float  g_gbuf[NPIX];     // exp(-sum d^2) image
__device__ double g_stats1[2];      // sum, sumsq of g
__device__ float  g_bn1c[2];        // a1, c1 : z = a1*g + c1
__device__ double g_S[9];           // per-tap sums of z (zero-padded shifts)
__device__ double g_P[45];          // upper-tri of 9x9 Gram of neighbor vec
__device__ float  g_w2p[CH*9];      // BN2-folded conv2 weights
__device__ float  g_b2p[CH];        // BN2-folded conv2 bias

// ---- packed f32x2 helpers (sm_100 PTX) ----
typedef unsigned long long u64p;
__device__ __forceinline__ u64p pk2(float lo, float hi) {
    u64p r; asm("mov.b64 %0,{%1,%2};" : "=l"(r) : "f"(lo), "f"(hi)); return r;
}
__device__ __forceinline__ void upk2(u64p v, float& lo, float& hi) {
    asm("mov.b64 {%0,%1},%2;" : "=f"(lo), "=f"(hi) : "l"(v));
}
__device__ __forceinline__ void fma2(u64p& d, u64p a, u64p b) {
    asm("fma.rn.f32x2 %0,%1,%2,%0;" : "+l"(d) : "l"(a), "l"(b));
}

// ---- cp.async 16B with zfill (src-size 0 -> zeros) ----
__device__ __forceinline__ void cp16_zfill(void* smem_dst, const void* gsrc, int sz) {
    unsigned saddr = (unsigned)__cvta_generic_to_shared(smem_dst);
    asm volatile("cp.async.cg.shared.global [%0], [%1], 16, %2;"
                 :: "r"(saddr), "l"(gsrc), "r"(sz) : "memory");
}

// ------------------------------------------------------------------
__global__ void k0_zero() {
    int t = threadIdx.x;
    if (t < 2)  g_stats1[t] = 0.0;
    if (t < 9)  g_S[t]      = 0.0;
    if (t < 45) g_P[t]      = 0.0;
}

// ------------------------------------------------------------------
// K1: conv1 (64ch -> 1ch, 3x3 SAME) + fuzzy + exp -> g_gbuf, BN1 stats.
// 256 threads = 64 (x, 4-col float4) x 4 (y, 4 rows each). Tile 16 rows.
// cp.async double-buffered over channels; packed f32x2 FMAs.
#define TH1 16
__global__ __launch_bounds__(256)
void k1_conv1(const float* __restrict__ x,  const float* __restrict__ cw1,
              const float* __restrict__ cb1, const float* __restrict__ mu,
              const float* __restrict__ sigma) {
    __shared__ float sA[2][TH1+2][WW];
    __shared__ float sw[CH*9];
    __shared__ float sr1[8], sr2[8];

    int tid = threadIdx.x;
    int txq = tid & 63;
    int ty  = tid >> 6;
    for (int i = tid; i < CH*9; i += 256) sw[i] = cw1[i];

    int rowstart = blockIdx.x * TH1;
    int b  = rowstart >> 8;
    int y0 = rowstart & 255;
    const float* xb = x + (size_t)b * CH * (HH*WW);

    u64p acc[4][2];
#pragma unroll
    for (int j = 0; j < 4; j++) { acc[j][0] = 0ULL; acc[j][1] = 0ULL; }

    // ---- async fill of one channel tile into buffer `buf` ----
    auto fill = [&](int c, int buf) {
        const float* xc = xb + (size_t)c * (HH*WW);
        for (int i = tid; i < (TH1+2)*64; i += 256) {
            int r  = i >> 6, c4 = i & 63;
            int gy = y0 - 1 + r;
            int inb = (gy >= 0 && gy < HH);
            const float* src = xc + (size_t)(inb ? gy : 0) * WW + c4*4;
            cp16_zfill(&sA[buf][r][c4*4], src, inb ? 16 : 0);
        }
        asm volatile("cp.async.commit_group;" ::: "memory");
    };

    fill(0, 0);
    for (int c = 0; c < CH; c++) {
        if (c + 1 < CH) {
            fill(c + 1, (c + 1) & 1);
            asm volatile("cp.async.wait_group 1;" ::: "memory");
        } else {
            asm volatile("cp.async.wait_group 0;" ::: "memory");
        }
        __syncthreads();
        int buf = c & 1;

        u64p wp[9];
#pragma unroll
        for (int k = 0; k < 9; k++) { float w = sw[c*9 + k]; wp[k] = pk2(w, w); }

#pragma unroll
        for (int r = 0; r < 6; r++) {
            int sr = 4*ty + r;
            float4 C4 = *reinterpret_cast<const float4*>(&sA[buf][sr][txq*4]);
            float lm = (txq > 0)  ? sA[buf][sr][txq*4 - 1] : 0.f;
            float rp = (txq < 63) ? sA[buf][sr][txq*4 + 4] : 0.f;
            u64p pLA = pk2(lm,   C4.x);
            u64p pCA = pk2(C4.x, C4.y);
            u64p pM  = pk2(C4.y, C4.z);   // R-tap of lo pair == L-tap of hi pair
            u64p pCB = pk2(C4.z, C4.w);
            u64p pRB = pk2(C4.w, rp);
#pragma unroll
            for (int k = 0; k < 3; k++) {
                int jo = r - k;
                if (jo >= 0 && jo < 4) {
                    fma2(acc[jo][0], pLA, wp[k*3+0]);
                    fma2(acc[jo][0], pCA, wp[k*3+1]);
                    fma2(acc[jo][0], pM,  wp[k*3+2]);
                    fma2(acc[jo][1], pM,  wp[k*3+0]);
                    fma2(acc[jo][1], pCB, wp[k*3+1]);
                    fma2(acc[jo][1], pRB, wp[k*3+2]);
                }
            }
        }
        __syncthreads();
    }

    // fuzzy membership + exp + store
    float bv = cb1[0];
    float m0 = mu[0], m1 = mu[1], m2 = mu[2], m3 = mu[3];
    float i0 = 1.f/sigma[0], i1 = 1.f/sigma[1], i2 = 1.f/sigma[2], i3 = 1.f/sigma[3];
    float lsum = 0.f, lsq = 0.f;
#pragma unroll
    for (int j = 0; j < 4; j++) {
        float h[4];
        upk2(acc[j][0], h[0], h[1]);
        upk2(acc[j][1], h[2], h[3]);
        float4 gv4;
        float* gp = &gv4.x;
#pragma unroll
        for (int e = 0; e < 4; e++) {
            float hh = h[e] + bv;
            float d0 = (hh-m0)*i0, d1 = (hh-m1)*i1, d2 = (hh-m2)*i2, d3 = (hh-m3)*i3;
            float t  = d0*d0 + d1*d1 + d2*d2 + d3*d3;
            float gv = __expf(-t);
            gp[e] = gv; lsum += gv; lsq += gv*gv;
        }
        int gy = rowstart + 4*ty + j;
        *reinterpret_cast<float4*>(&g_gbuf[gy*WW + txq*4]) = gv4;
    }

    int lane = tid & 31, wid = tid >> 5;
#pragma unroll
    for (int o = 16; o; o >>= 1) {
        lsum += __shfl_down_sync(0xffffffffu, lsum, o);
        lsq  += __shfl_down_sync(0xffffffffu, lsq,  o);
    }
    if (lane == 0) { sr1[wid] = lsum; sr2[wid] = lsq; }
    __syncthreads();
    if (tid == 0) {
        double S = 0.0, Q = 0.0;
        for (int w = 0; w < 8; w++) { S += (double)sr1[w]; Q += (double)sr2[w]; }
        atomicAdd(&g_stats1[0], S);
        atomicAdd(&g_stats1[1], Q);
    }
}

// ------------------------------------------------------------------
__global__ void k2_bn1(const float* __restrict__ bn1_g, const float* __restrict__ bn1_b) {
    double N    = (double)NPIX;
    double mean = g_stats1[0] / N;
    double var  = g_stats1[1] / N - mean*mean;
    double a    = (double)bn1_g[0] / sqrt(var + 1e-5);
    g_bn1c[0] = (float)a;
    g_bn1c[1] = (float)((double)bn1_b[0] - mean*a);
}

// ------------------------------------------------------------------
// K3: accumulate S[9] and Gram P[45] of the zero-padded 3x3 neighbor
// vector of z = a1*g + c1 (exactly matches conv2 SAME padding).
#define TH3 16
__global__ __launch_bounds__(256)
void k3_stats() {
    __shared__ float s[TH3+2][WW];
    __shared__ float sred[8][54];

    float a1 = g_bn1c[0], c1 = g_bn1c[1];
    int tx = threadIdx.x;
    int rowstart = blockIdx.x * TH3;
    int b  = rowstart >> 8;
    int y0 = rowstart & 255;

#pragma unroll
    for (int r = 0; r < TH3+2; r++) {
        int gy = y0 - 1 + r;
        s[r][tx] = (gy >= 0 && gy < HH)
                   ? fmaf(a1, g_gbuf[(b*HH+gy)*WW + tx], c1) : 0.f;
    }
    __syncthreads();

    float acc[54];
#pragma unroll
    for (int i = 0; i < 54; i++) acc[i] = 0.f;

#pragma unroll
    for (int j = 0; j < TH3; j++) {
        float n[9];
#pragma unroll
        for (int ky = 0; ky < 3; ky++) {
            int r = j + ky;
            float C = s[r][tx];
            float L = (tx > 0)    ? s[r][tx-1] : 0.f;
            float R = (tx < WW-1) ? s[r][tx+1] : 0.f;
            n[ky*3+0] = L; n[ky*3+1] = C; n[ky*3+2] = R;
        }
#pragma unroll
        for (int a = 0; a < 9; a++) acc[a] += n[a];
        int t = 9;
#pragma unroll
        for (int a = 0; a < 9; a++)
#pragma unroll
            for (int bb = a; bb < 9; bb++) { acc[t] += n[a]*n[bb]; t++; }
    }

    int lane = tx & 31, wid = tx >> 5;
#pragma unroll
    for (int k = 0; k < 54; k++) {
        float v = acc[k];
#pragma unroll
        for (int o = 16; o; o >>= 1) v += __shfl_down_sync(0xffffffffu, v, o);
        if (lane == 0) sred[wid][k] = v;
    }
    __syncthreads();
    if (tx < 54) {
        double v = 0.0;
        for (int w = 0; w < 8; w++) v += (double)sred[w][tx];
        if (tx < 9) atomicAdd(&g_S[tx], v);
        else        atomicAdd(&g_P[tx-9], v);
    }
}

// ------------------------------------------------------------------
// K4: analytic BN2 stats from S, P -> fold into conv2 weights/bias.
__global__ void k4_bn2(const float* __restrict__ w2, const float* __restrict__ b2,
                       const float* __restrict__ g2, const float* __restrict__ be2) {
    int o = threadIdx.x;
    if (o >= CH) return;
    double S[9];
    for (int k = 0; k < 9; k++) S[k] = g_S[k];
    double Pm[9][9];
    int t = 0;
    for (int a = 0; a < 9; a++)
        for (int bb = a; bb < 9; bb++) {
            double v = g_P[t++]; Pm[a][bb] = v; Pm[bb][a] = v;
        }
    double w[9];
    for (int k = 0; k < 9; k++) w[k] = (double)w2[o*9+k];
    double bo = (double)b2[o];
    double ws = 0.0;
    for (int k = 0; k < 9; k++) ws += w[k]*S[k];
    double quad = 0.0;
    for (int a = 0; a < 9; a++) {
        double r = 0.0;
        for (int bb = 0; bb < 9; bb++) r += Pm[a][bb]*w[bb];
        quad += w[a]*r;
    }
    double N    = (double)NPIX;
    double mean = (ws + N*bo) / N;
    double m2   = (quad + 2.0*bo*ws + N*bo*bo) / N;
    double var  = m2 - mean*mean;
    double sc   = (double)g2[o] / sqrt(var + 1e-5);
    for (int k = 0; k < 9; k++) g_w2p[o*9+k] = (float)(w[k]*sc);
    g_b2p[o] = (float)(((double)bo - mean)*sc + (double)be2[o]);
}

// ------------------------------------------------------------------
// K5: conv2' (1ch -> 64ch, folded BN2) -> out. BN1 affine applied on the
// fly while staging z into smem (zero padding preserved). Packed f32x2.
#define TH5  16
#define OGRP 16
__global__ __launch_bounds__(256)
void k5_conv2(float* __restrict__ out) {
    __shared__ float s[TH5+2][WW];
    __shared__ float swp[CH*9];
    __shared__ float sbp[CH];

    int tid = threadIdx.x;
    int txq = tid & 63;
    int ty  = tid >> 6;
    int tile = blockIdx.x >> 2;          // 256 tiles
    int grp  = blockIdx.x & 3;           // 4 channel groups of 16
    int rowstart = tile * TH5;
    int b  = rowstart >> 8;
    int y0 = rowstart & 255;

    float a1 = g_bn1c[0], c1 = g_bn1c[1];
    for (int i = tid; i < CH*9; i += 256) swp[i] = g_w2p[i];
    if (tid < CH) sbp[tid] = g_b2p[tid];

    for (int i = tid; i < (TH5+2)*64; i += 256) {
        int r = i >> 6, c4 = i & 63;
        int gy = y0 - 1 + r;
        float4 v;
        if (gy >= 0 && gy < HH) {
            v = *reinterpret_cast<const float4*>(&g_gbuf[(b*HH+gy)*WW + c4*4]);
            v.x = fmaf(a1, v.x, c1); v.y = fmaf(a1, v.y, c1);
            v.z = fmaf(a1, v.z, c1); v.w = fmaf(a1, v.w, c1);
        } else {
            v = make_float4(0.f, 0.f, 0.f, 0.f);
        }
        *reinterpret_cast<float4*>(&s[r][c4*4]) = v;
    }
    __syncthreads();

    size_t obase = (size_t)b * CH * (HH*WW);
    for (int oo = 0; oo < OGRP; oo++) {
        int o = grp*OGRP + oo;
        u64p wp[9];
#pragma unroll
        for (int k = 0; k < 9; k++) { float w = swp[o*9 + k]; wp[k] = pk2(w, w); }
        float bb = sbp[o];
        u64p bbp = pk2(bb, bb);
        u64p acc[4][2];
#pragma unroll
        for (int j = 0; j < 4; j++) { acc[j][0] = bbp; acc[j][1] = bbp; }

#pragma unroll
        for (int r = 0; r < 6; r++) {
            int sr = 4*ty + r;
            float4 C4 = *reinterpret_cast<const float4*>(&s[sr][txq*4]);
            float lm = (txq > 0)  ? s[sr][txq*4 - 1] : 0.f;
            float rp = (txq < 63) ? s[sr][txq*4 + 4] : 0.f;
            u64p pLA = pk2(lm,   C4.x);
            u64p pCA = pk2(C4.x, C4.y);
            u64p pM  = pk2(C4.y, C4.z);
            u64p pCB = pk2(C4.z, C4.w);
            u64p pRB = pk2(C4.w, rp);
#pragma unroll
            for (int k = 0; k < 3; k++) {
                int jo = r - k;
                if (jo >= 0 && jo < 4) {
                    fma2(acc[jo][0], pLA, wp[k*3+0]);
                    fma2(acc[jo][0], pCA, wp[k*3+1]);
                    fma2(acc[jo][0], pM,  wp[k*3+2]);
                    fma2(acc[jo][1], pM,  wp[k*3+0]);
                    fma2(acc[jo][1], pCB, wp[k*3+1]);
                    fma2(acc[jo][1], pRB, wp[k*3+2]);
                }
            }
        }

        float* op = out + obase + (size_t)o*(HH*WW) + (size_t)(y0 + 4*ty)*WW + txq*4;
#pragma unroll
        for (int j = 0; j < 4; j++) {
            float4 v;
            upk2(acc[j][0], v.x, v.y);
            upk2(acc[j][1], v.z, v.w);
            *reinterpret_cast<float4*>(op + j*WW) = v;
        }
    }
}

// ------------------------------------------------------------------
extern "C" void kernel_launch(void* const* d_in, const int* in_sizes, int n_in,
                              void* d_out, int out_size) {
    const float* x   = (const float*)d_in[0];
    const float* w1  = (const float*)d_in[1];
    const float* b1  = (const float*)d_in[2];
    const float* w2  = (const float*)d_in[3];
    const float* b2  = (const float*)d_in[4];
    const float* mu  = (const float*)d_in[5];
    const float* sg  = (const float*)d_in[6];
    const float* g1  = (const float*)d_in[7];
    const float* bb1 = (const float*)d_in[8];
    const float* g2  = (const float*)d_in[9];
    const float* bb2 = (const float*)d_in[10];
    float* out = (float*)d_out;

    k0_zero <<<1, 64>>>();
    k1_conv1<<<ROWS/TH1, 256>>>(x, w1, b1, mu, sg);
    k2_bn1  <<<1, 1>>>(g1, bb1);
    k3_stats<<<ROWS/TH3, 256>>>();
    k4_bn2  <<<1, CH>>>(w2, b2, g2, bb2);
    k5_conv2<<<(ROWS/TH5)*4, 256>>>(out);
}

// round 5
// speedup vs baseline: 2.1162x; 1.1261x over previous
#include <cuda_runtime.h>
#include <math.h>

#define BATCH 16
#define CH    64
#define HH    256
#define WW    256
#define NPIX  (BATCH*HH*WW)   /* 1048576 */
#define ROWS  (BATCH*HH)      /* 4096    */
#define NSPLIT 4
#define CSPL   (CH/NSPLIT)    /* 16 channels per split */

// ---- scratch (device globals: no allocation allowed) ----
__device__ float  g_part[NSPLIT*NPIX]; // partial conv1 sums (4 x 4 MB)
__device__ float  g_gbuf[NPIX];        // exp(-sum d^2) image
__device__ double g_stats1[2];         // sum, sumsq of g
__device__ float  g_bn1c[2];           // a1, c1 : z = a1*g + c1
__device__ double g_S[9];              // per-tap sums of z (zero-padded shifts)
__device__ double g_P[45];             // upper-tri of 9x9 Gram of neighbor vec
__device__ float  g_w2p[CH*9];         // BN2-folded conv2 weights
__device__ float  g_b2p[CH];           // BN2-folded conv2 bias

// ---- packed f32x2 helpers (sm_100 PTX) ----
typedef unsigned long long u64p;
__device__ __forceinline__ u64p pk2(float lo, float hi) {
    u64p r; asm("mov.b64 %0,{%1,%2};" : "=l"(r) : "f"(lo), "f"(hi)); return r;
}
__device__ __forceinline__ void upk2(u64p v, float& lo, float& hi) {
    asm("mov.b64 {%0,%1},%2;" : "=f"(lo), "=f"(hi) : "l"(v));
}
__device__ __forceinline__ void fma2(u64p& d, u64p a, u64p b) {
    asm("fma.rn.f32x2 %0,%1,%2,%0;" : "+l"(d) : "l"(a), "l"(b));
}

// ---- cp.async 16B with zfill (src-size 0 -> zeros) ----
__device__ __forceinline__ void cp16_zfill(void* smem_dst, const void* gsrc, int sz) {
    unsigned saddr = (unsigned)__cvta_generic_to_shared(smem_dst);
    asm volatile("cp.async.cg.shared.global [%0], [%1], 16, %2;"
                 :: "r"(saddr), "l"(gsrc), "r"(sz) : "memory");
}

// ------------------------------------------------------------------
__global__ void k0_zero() {
    int t = threadIdx.x;
    if (t < 2)  g_stats1[t] = 0.0;
    if (t < 9)  g_S[t]      = 0.0;
    if (t < 45) g_P[t]      = 0.0;
}

// ------------------------------------------------------------------
// K1: partial conv1 over 16 channels -> g_part[split]. 1024 blocks.
// 256 threads = 64 (x, float4 cols) x 4 (y, 4 rows). Tile 16 rows.
#define TH1 16
__global__ __launch_bounds__(256)
void k1_conv1(const float* __restrict__ x, const float* __restrict__ cw1) {
    __shared__ float sA[2][TH1+2][WW];
    __shared__ float sw[CSPL*9];

    int tid  = threadIdx.x;
    int txq  = tid & 63;
    int ty   = tid >> 6;
    int tile = blockIdx.x >> 2;
    int spl  = blockIdx.x & 3;
    int cb   = spl * CSPL;

    for (int i = tid; i < CSPL*9; i += 256) sw[i] = cw1[cb*9 + i];

    int rowstart = tile * TH1;
    int b  = rowstart >> 8;
    int y0 = rowstart & 255;
    const float* xb = x + (size_t)b * CH * (HH*WW);

    u64p acc[4][2];
#pragma unroll
    for (int j = 0; j < 4; j++) { acc[j][0] = 0ULL; acc[j][1] = 0ULL; }

    auto fill = [&](int ci, int buf) {
        const float* xc = xb + (size_t)(cb + ci) * (HH*WW);
        for (int i = tid; i < (TH1+2)*64; i += 256) {
            int r  = i >> 6, c4 = i & 63;
            int gy = y0 - 1 + r;
            int inb = (gy >= 0 && gy < HH);
            const float* src = xc + (size_t)(inb ? gy : 0) * WW + c4*4;
            cp16_zfill(&sA[buf][r][c4*4], src, inb ? 16 : 0);
        }
        asm volatile("cp.async.commit_group;" ::: "memory");
    };

    fill(0, 0);
    for (int ci = 0; ci < CSPL; ci++) {
        if (ci + 1 < CSPL) {
            fill(ci + 1, (ci + 1) & 1);
            asm volatile("cp.async.wait_group 1;" ::: "memory");
        } else {
            asm volatile("cp.async.wait_group 0;" ::: "memory");
        }
        __syncthreads();
        int buf = ci & 1;

        u64p wp[9];
#pragma unroll
        for (int k = 0; k < 9; k++) { float w = sw[ci*9 + k]; wp[k] = pk2(w, w); }

#pragma unroll
        for (int r = 0; r < 6; r++) {
            int sr = 4*ty + r;
            float4 C4 = *reinterpret_cast<const float4*>(&sA[buf][sr][txq*4]);
            float lm = (txq > 0)  ? sA[buf][sr][txq*4 - 1] : 0.f;
            float rp = (txq < 63) ? sA[buf][sr][txq*4 + 4] : 0.f;
            u64p pLA = pk2(lm,   C4.x);
            u64p pCA = pk2(C4.x, C4.y);
            u64p pM  = pk2(C4.y, C4.z);
            u64p pCB = pk2(C4.z, C4.w);
            u64p pRB = pk2(C4.w, rp);
#pragma unroll
            for (int k = 0; k < 3; k++) {
                int jo = r - k;
                if (jo >= 0 && jo < 4) {
                    fma2(acc[jo][0], pLA, wp[k*3+0]);
                    fma2(acc[jo][0], pCA, wp[k*3+1]);
                    fma2(acc[jo][0], pM,  wp[k*3+2]);
                    fma2(acc[jo][1], pM,  wp[k*3+0]);
                    fma2(acc[jo][1], pCB, wp[k*3+1]);
                    fma2(acc[jo][1], pRB, wp[k*3+2]);
                }
            }
        }
        __syncthreads();
    }

    float* pout = g_part + (size_t)spl * NPIX;
#pragma unroll
    for (int j = 0; j < 4; j++) {
        float4 v;
        upk2(acc[j][0], v.x, v.y);
        upk2(acc[j][1], v.z, v.w);
        int gy = rowstart + 4*ty + j;
        *reinterpret_cast<float4*>(&pout[gy*WW + txq*4]) = v;
    }
}

// ------------------------------------------------------------------
// K1b: sum partials + bias + fuzzy + exp -> g_gbuf, BN1 stats. 1024 blocks.
__global__ __launch_bounds__(256)
void k1b_finish(const float* __restrict__ cb1, const float* __restrict__ mu,
                const float* __restrict__ sigma) {
    __shared__ float sr1[8], sr2[8];
    int tid = threadIdx.x;
    int idx = (blockIdx.x * 256 + tid) * 4;

    float4 a = *reinterpret_cast<const float4*>(&g_part[idx]);
    float4 bq = *reinterpret_cast<const float4*>(&g_part[NPIX + idx]);
    float4 cq = *reinterpret_cast<const float4*>(&g_part[2*NPIX + idx]);
    float4 dq = *reinterpret_cast<const float4*>(&g_part[3*NPIX + idx]);

    float bv = cb1[0];
    float m0 = mu[0], m1 = mu[1], m2 = mu[2], m3 = mu[3];
    float i0 = 1.f/sigma[0], i1 = 1.f/sigma[1], i2 = 1.f/sigma[2], i3 = 1.f/sigma[3];

    float h[4] = { a.x+bq.x+cq.x+dq.x, a.y+bq.y+cq.y+dq.y,
                   a.z+bq.z+cq.z+dq.z, a.w+bq.w+cq.w+dq.w };
    float4 gv4; float* gp = &gv4.x;
    float lsum = 0.f, lsq = 0.f;
#pragma unroll
    for (int e = 0; e < 4; e++) {
        float hh = h[e] + bv;
        float d0 = (hh-m0)*i0, d1 = (hh-m1)*i1, d2 = (hh-m2)*i2, d3 = (hh-m3)*i3;
        float t  = d0*d0 + d1*d1 + d2*d2 + d3*d3;
        float gv = __expf(-t);
        gp[e] = gv; lsum += gv; lsq += gv*gv;
    }
    *reinterpret_cast<float4*>(&g_gbuf[idx]) = gv4;

    int lane = tid & 31, wid = tid >> 5;
#pragma unroll
    for (int o = 16; o; o >>= 1) {
        lsum += __shfl_down_sync(0xffffffffu, lsum, o);
        lsq  += __shfl_down_sync(0xffffffffu, lsq,  o);
    }
    if (lane == 0) { sr1[wid] = lsum; sr2[wid] = lsq; }
    __syncthreads();
    if (tid == 0) {
        double S = 0.0, Q = 0.0;
        for (int w = 0; w < 8; w++) { S += (double)sr1[w]; Q += (double)sr2[w]; }
        atomicAdd(&g_stats1[0], S);
        atomicAdd(&g_stats1[1], Q);
    }
}

// ------------------------------------------------------------------
__global__ void k2_bn1(const float* __restrict__ bn1_g, const float* __restrict__ bn1_b) {
    double N    = (double)NPIX;
    double mean = g_stats1[0] / N;
    double var  = g_stats1[1] / N - mean*mean;
    double a    = (double)bn1_g[0] / sqrt(var + 1e-5);
    g_bn1c[0] = (float)a;
    g_bn1c[1] = (float)((double)bn1_b[0] - mean*a);
}

// ------------------------------------------------------------------
// K3: accumulate S[9] and Gram P[45] of the zero-padded 3x3 neighbor
// vector of z = a1*g + c1. TH3=8 rows/block -> 512 blocks.
#define TH3 8
__global__ __launch_bounds__(256)
void k3_stats() {
    __shared__ float s[TH3+2][WW];
    __shared__ float sred[8][54];

    float a1 = g_bn1c[0], c1 = g_bn1c[1];
    int tx = threadIdx.x;
    int rowstart = blockIdx.x * TH3;
    int b  = rowstart >> 8;
    int y0 = rowstart & 255;

#pragma unroll
    for (int r = 0; r < TH3+2; r++) {
        int gy = y0 - 1 + r;
        s[r][tx] = (gy >= 0 && gy < HH)
                   ? fmaf(a1, g_gbuf[(b*HH+gy)*WW + tx], c1) : 0.f;
    }
    __syncthreads();

    float acc[54];
#pragma unroll
    for (int i = 0; i < 54; i++) acc[i] = 0.f;

#pragma unroll
    for (int j = 0; j < TH3; j++) {
        float n[9];
#pragma unroll
        for (int ky = 0; ky < 3; ky++) {
            int r = j + ky;
            float C = s[r][tx];
            float L = (tx > 0)    ? s[r][tx-1] : 0.f;
            float R = (tx < WW-1) ? s[r][tx+1] : 0.f;
            n[ky*3+0] = L; n[ky*3+1] = C; n[ky*3+2] = R;
        }
#pragma unroll
        for (int a = 0; a < 9; a++) acc[a] += n[a];
        int t = 9;
#pragma unroll
        for (int a = 0; a < 9; a++)
#pragma unroll
            for (int bb = a; bb < 9; bb++) { acc[t] += n[a]*n[bb]; t++; }
    }

    int lane = tx & 31, wid = tx >> 5;
#pragma unroll
    for (int k = 0; k < 54; k++) {
        float v = acc[k];
#pragma unroll
        for (int o = 16; o; o >>= 1) v += __shfl_down_sync(0xffffffffu, v, o);
        if (lane == 0) sred[wid][k] = v;
    }
    __syncthreads();
    if (tx < 54) {
        double v = 0.0;
        for (int w = 0; w < 8; w++) v += (double)sred[w][tx];
        if (tx < 9) atomicAdd(&g_S[tx], v);
        else        atomicAdd(&g_P[tx-9], v);
    }
}

// ------------------------------------------------------------------
// K4: analytic BN2 stats from S, P -> fold into conv2 weights/bias.
__global__ void k4_bn2(const float* __restrict__ w2, const float* __restrict__ b2,
                       const float* __restrict__ g2, const float* __restrict__ be2) {
    int o = threadIdx.x;
    if (o >= CH) return;
    double S[9];
    for (int k = 0; k < 9; k++) S[k] = g_S[k];
    double Pm[9][9];
    int t = 0;
    for (int a = 0; a < 9; a++)
        for (int bb = a; bb < 9; bb++) {
            double v = g_P[t++]; Pm[a][bb] = v; Pm[bb][a] = v;
        }
    double w[9];
    for (int k = 0; k < 9; k++) w[k] = (double)w2[o*9+k];
    double bo = (double)b2[o];
    double ws = 0.0;
    for (int k = 0; k < 9; k++) ws += w[k]*S[k];
    double quad = 0.0;
    for (int a = 0; a < 9; a++) {
        double r = 0.0;
        for (int bb = 0; bb < 9; bb++) r += Pm[a][bb]*w[bb];
        quad += w[a]*r;
    }
    double N    = (double)NPIX;
    double mean = (ws + N*bo) / N;
    double m2   = (quad + 2.0*bo*ws + N*bo*bo) / N;
    double var  = m2 - mean*mean;
    double sc   = (double)g2[o] / sqrt(var + 1e-5);
    for (int k = 0; k < 9; k++) g_w2p[o*9+k] = (float)(w[k]*sc);
    g_b2p[o] = (float)(((double)bo - mean)*sc + (double)be2[o]);
}

// ------------------------------------------------------------------
// K5: conv2' (1ch -> 64ch, folded BN2) -> out. BN1 affine applied on the
// fly while staging z into smem (zero padding preserved). Packed f32x2.
#define TH5  16
#define OGRP 16
__global__ __launch_bounds__(256)
void k5_conv2(float* __restrict__ out) {
    __shared__ float s[TH5+2][WW];
    __shared__ float swp[CH*9];
    __shared__ float sbp[CH];

    int tid = threadIdx.x;
    int txq = tid & 63;
    int ty  = tid >> 6;
    int tile = blockIdx.x >> 2;
    int grp  = blockIdx.x & 3;
    int rowstart = tile * TH5;
    int b  = rowstart >> 8;
    int y0 = rowstart & 255;

    float a1 = g_bn1c[0], c1 = g_bn1c[1];
    for (int i = tid; i < CH*9; i += 256) swp[i] = g_w2p[i];
    if (tid < CH) sbp[tid] = g_b2p[tid];

    for (int i = tid; i < (TH5+2)*64; i += 256) {
        int r = i >> 6, c4 = i & 63;
        int gy = y0 - 1 + r;
        float4 v;
        if (gy >= 0 && gy < HH) {
            v = *reinterpret_cast<const float4*>(&g_gbuf[(b*HH+gy)*WW + c4*4]);
            v.x = fmaf(a1, v.x, c1); v.y = fmaf(a1, v.y, c1);
            v.z = fmaf(a1, v.z, c1); v.w = fmaf(a1, v.w, c1);
        } else {
            v = make_float4(0.f, 0.f, 0.f, 0.f);
        }
        *reinterpret_cast<float4*>(&s[r][c4*4]) = v;
    }
    __syncthreads();

    size_t obase = (size_t)b * CH * (HH*WW);
    for (int oo = 0; oo < OGRP; oo++) {
        int o = grp*OGRP + oo;
        u64p wp[9];
#pragma unroll
        for (int k = 0; k < 9; k++) { float w = swp[o*9 + k]; wp[k] = pk2(w, w); }
        float bb = sbp[o];
        u64p bbp = pk2(bb, bb);
        u64p acc[4][2];
#pragma unroll
        for (int j = 0; j < 4; j++) { acc[j][0] = bbp; acc[j][1] = bbp; }

#pragma unroll
        for (int r = 0; r < 6; r++) {
            int sr = 4*ty + r;
            float4 C4 = *reinterpret_cast<const float4*>(&s[sr][txq*4]);
            float lm = (txq > 0)  ? s[sr][txq*4 - 1] : 0.f;
            float rp = (txq < 63) ? s[sr][txq*4 + 4] : 0.f;
            u64p pLA = pk2(lm,   C4.x);
            u64p pCA = pk2(C4.x, C4.y);
            u64p pM  = pk2(C4.y, C4.z);
            u64p pCB = pk2(C4.z, C4.w);
            u64p pRB = pk2(C4.w, rp);
#pragma unroll
            for (int k = 0; k < 3; k++) {
                int jo = r - k;
                if (jo >= 0 && jo < 4) {
                    fma2(acc[jo][0], pLA, wp[k*3+0]);
                    fma2(acc[jo][0], pCA, wp[k*3+1]);
                    fma2(acc[jo][0], pM,  wp[k*3+2]);
                    fma2(acc[jo][1], pM,  wp[k*3+0]);
                    fma2(acc[jo][1], pCB, wp[k*3+1]);
                    fma2(acc[jo][1], pRB, wp[k*3+2]);
                }
            }
        }

        float* op = out + obase + (size_t)o*(HH*WW) + (size_t)(y0 + 4*ty)*WW + txq*4;
#pragma unroll
        for (int j = 0; j < 4; j++) {
            float4 v;
            upk2(acc[j][0], v.x, v.y);
            upk2(acc[j][1], v.z, v.w);
            *reinterpret_cast<float4*>(op + j*WW) = v;
        }
    }
}

// ------------------------------------------------------------------
extern "C" void kernel_launch(void* const* d_in, const int* in_sizes, int n_in,
                              void* d_out, int out_size) {
    const float* x   = (const float*)d_in[0];
    const float* w1  = (const float*)d_in[1];
    const float* b1  = (const float*)d_in[2];
    const float* w2  = (const float*)d_in[3];
    const float* b2  = (const float*)d_in[4];
    const float* mu  = (const float*)d_in[5];
    const float* sg  = (const float*)d_in[6];
    const float* g1  = (const float*)d_in[7];
    const float* bb1 = (const float*)d_in[8];
    const float* g2  = (const float*)d_in[9];
    const float* bb2 = (const float*)d_in[10];
    float* out = (float*)d_out;

    k0_zero   <<<1, 64>>>();
    k1_conv1  <<<(ROWS/TH1)*NSPLIT, 256>>>(x, w1);
    k1b_finish<<<NPIX/1024, 256>>>(b1, mu, sg);
    k2_bn1    <<<1, 1>>>(g1, bb1);
    k3_stats  <<<ROWS/TH3, 256>>>();
    k4_bn2    <<<1, CH>>>(w2, b2, g2, bb2);
    k5_conv2  <<<(ROWS/TH5)*4, 256>>>(out);
}